// round 8
// baseline (speedup 1.0000x reference)
#include <cuda_runtime.h>
#include <cuda_bf16.h>
#include <stdint.h>

// Problem constants (B=1, N=256, L=192, J=32, d2=1024, F=128)
#define LDIM 192
#define NDIM 256      // K of GEMM1
#define RDIM 6144     // L*J  (M=N of GEMM1)
#define D2   1024     // J*J  (K of GEMM2)
#define FDIM 128      // N of GEMM2
#define M2   36864    // L*L  (M of GEMM2)

// ---------------------------------------------------------------------------
// Scratch (__device__ globals; no runtime allocation)
// ---------------------------------------------------------------------------
__device__ __nv_bfloat16 g_Ah[(size_t)RDIM * NDIM];   // x_down^T  hi  [r][n]
__device__ __nv_bfloat16 g_Al[(size_t)RDIM * NDIM];   //           lo
__device__ __nv_bfloat16 g_Bh[(size_t)RDIM * NDIM];   // x_down_w^T hi
__device__ __nv_bfloat16 g_Bl[(size_t)RDIM * NDIM];
__device__ __nv_bfloat16 g_Ph[(size_t)M2 * D2];       // pair hi [(i*192+l)][j*32+m]
__device__ __nv_bfloat16 g_Pl[(size_t)M2 * D2];       // pair lo
__device__ __nv_bfloat16 g_Wth[(size_t)FDIM * D2];    // (a2*W)^T hi [f][k]
__device__ __nv_bfloat16 g_Wtl[(size_t)FDIM * D2];
__device__ float g_mu[M2];
__device__ float g_rs[M2];
__device__ float g_c1[FDIM];
__device__ float g_c2[FDIM];

// ---------------------------------------------------------------------------
// Family-portable PTX helpers (compute_103-safe: mma.sync / ldmatrix / cp.async)
// ---------------------------------------------------------------------------
__device__ __forceinline__ uint32_t smem_u32(const void* p) {
    uint32_t a;
    asm("{ .reg .u64 t; cvta.to.shared.u64 t, %1; cvt.u32.u64 %0, t; }" : "=r"(a) : "l"(p));
    return a;
}
__device__ __forceinline__ void cp16(uint32_t dst, const void* src) {
    asm volatile("cp.async.cg.shared.global [%0], [%1], 16;" :: "r"(dst), "l"(src) : "memory");
}
__device__ __forceinline__ void cp_commit() {
    asm volatile("cp.async.commit_group;" ::: "memory");
}
template <int N>
__device__ __forceinline__ void cp_wait() {
    asm volatile("cp.async.wait_group %0;" :: "n"(N) : "memory");
}
__device__ __forceinline__ void ldm4(uint32_t a[4], uint32_t addr) {
    asm volatile("ldmatrix.sync.aligned.m8n8.x4.shared.b16 {%0,%1,%2,%3}, [%4];"
                 : "=r"(a[0]), "=r"(a[1]), "=r"(a[2]), "=r"(a[3]) : "r"(addr));
}
// x4 B-load: two adjacent 8-col n-tiles (b0, b1), both k-halves each.
// Tile order: lanes0-7 rows n..n+7 chunk0 -> b0[0]; lanes8-15 rows n+8..15 chunk0 -> b1[0];
//             lanes16-23 chunk1 -> b0[1]; lanes24-31 -> b1[1].
__device__ __forceinline__ void ldm4B(uint32_t b0[2], uint32_t b1[2], uint32_t addr) {
    asm volatile("ldmatrix.sync.aligned.m8n8.x4.shared.b16 {%0,%1,%2,%3}, [%4];"
                 : "=r"(b0[0]), "=r"(b1[0]), "=r"(b0[1]), "=r"(b1[1]) : "r"(addr));
}
__device__ __forceinline__ void mma16816(float c[4], const uint32_t a[4], const uint32_t b[2]) {
    asm volatile(
        "mma.sync.aligned.m16n8k16.row.col.f32.bf16.bf16.f32 "
        "{%0,%1,%2,%3}, {%4,%5,%6,%7}, {%8,%9}, {%0,%1,%2,%3};"
        : "+f"(c[0]), "+f"(c[1]), "+f"(c[2]), "+f"(c[3])
        : "r"(a[0]), "r"(a[1]), "r"(a[2]), "r"(a[3]), "r"(b[0]), "r"(b[1]));
}

// SMEM tile: 128 rows x 16 bf16 (32B/row), 2x16B chunks.
// Swizzle XORs the chunk bit with (r>>2)&1 so 8 rows at one chunk parity hit
// 8 DISTINCT 16B slots mod 128B -> conflict-free ldmatrix phases.
// (Old r&1 swizzle left rows r and r+4 128B apart = same banks = 2-way conflict.)
__device__ __forceinline__ uint32_t sw(int r, int c2) {
    return (uint32_t)(r * 32 + ((c2 ^ ((r >> 2) & 1)) << 4));
}

// SMEM layout per stage (16 KB): Ah[0:4K) Al[4K:8K) Bh[8K:12K) Bl[12K:16K)
#define STAGE_BYTES 16384
#define NSTAGE 3
#define SMEM_BYTES  (NSTAGE * STAGE_BYTES)   // 48 KB static

// ---------------------------------------------------------------------------
// Shared mainloop: 128x128 CTA tile, 8 warps (2x4), warp tile 64x32,
// K-chunk 16, 3-stage cp.async ring, one barrier per chunk,
// 3-MMA bf16 hi/lo split (split-major issue order).
// ---------------------------------------------------------------------------
__device__ __forceinline__ void mainloop(
    uint32_t sb, int NC,
    const __nv_bfloat16* __restrict__ Ah, const __nv_bfloat16* __restrict__ Al, int lda,
    const __nv_bfloat16* __restrict__ Bh, const __nv_bfloat16* __restrict__ Bl, int ldb,
    float acc[4][4][4])
{
    const int tid = threadIdx.x, lane = tid & 31;
    const int wr = tid >> 7;           // warp row 0..1 (64 rows each)
    const int wc = (tid >> 5) & 3;     // warp col 0..3 (32 cols each)

    // global->smem: 1 uint4 per tile per thread (256 threads = 128 rows x 2 chunks)
    const int r = tid >> 1, c2 = tid & 1;
    const uint32_t so = sw(r, c2);
    const char* pAh = (const char*)(Ah + (size_t)r * lda) + c2 * 16;
    const char* pAl = (const char*)(Al + (size_t)r * lda) + c2 * 16;
    const char* pBh = (const char*)(Bh + (size_t)r * ldb) + c2 * 16;
    const char* pBl = (const char*)(Bl + (size_t)r * ldb) + c2 * 16;

    // ldmatrix fragment base offsets.
    // Offsets +mt*512 / +nt*256 keep (r>>2)&1 parity -> swizzle-consistent.
    const uint32_t abase = sw(wr * 64 + (lane & 15), lane >> 4);
    const uint32_t bbase4 = sw(wc * 32 + (lane & 15), lane >> 4);

#define ISSUE_CHUNK(ck, st) do {                                   \
        uint32_t _b = sb + (uint32_t)(st) * STAGE_BYTES;           \
        size_t _ko = (size_t)(ck) * 32;                            \
        cp16(_b + so,          pAh + _ko);                         \
        cp16(_b + 4096u + so,  pAl + _ko);                         \
        cp16(_b + 8192u + so,  pBh + _ko);                         \
        cp16(_b + 12288u + so, pBl + _ko);                         \
    } while (0)

    // prologue: chunks 0,1 -> stages 0,1
    ISSUE_CHUNK(0, 0); cp_commit();
    if (NC > 1) ISSUE_CHUNK(1, 1);
    cp_commit();

#pragma unroll 1
    for (int c = 0; c < NC; ++c) {
        const int st = c % NSTAGE;
        cp_wait<1>();          // chunk c resident
        __syncthreads();       // all warps done reading stage (c-1)%3

        const uint32_t Ab = sb + (uint32_t)st * STAGE_BYTES;
        const uint32_t Bb = Ab + 8192u;

        // B fragments first (frees the hazard window for the prefetch below)
        uint32_t bh[4][2], bl[4][2];
        ldm4B(bh[0], bh[1], Bb + bbase4);
        ldm4B(bh[2], bh[3], Bb + bbase4 + 512u);
        ldm4B(bl[0], bl[1], Bb + 4096u + bbase4);
        ldm4B(bl[2], bl[3], Bb + 4096u + bbase4 + 512u);

        // prefetch chunk c+2 into stage (c+2)%3 == (c-1)%3 (safe: post-barrier)
        if (c + 2 < NC) ISSUE_CHUNK(c + 2, (c + 2) % NSTAGE);
        cp_commit();

#pragma unroll
        for (int mt = 0; mt < 4; ++mt) {
            uint32_t ah[4], al[4];
            ldm4(ah, Ab + abase + mt * 512u);
            ldm4(al, Ab + 4096u + abase + mt * 512u);
#pragma unroll
            for (int nt = 0; nt < 4; ++nt) mma16816(acc[mt][nt], ah, bh[nt]);  // hi*hi
#pragma unroll
            for (int nt = 0; nt < 4; ++nt) mma16816(acc[mt][nt], ah, bl[nt]);  // hi*lo
#pragma unroll
            for (int nt = 0; nt < 4; ++nt) mma16816(acc[mt][nt], al, bh[nt]);  // lo*hi
        }
    }
#undef ISSUE_CHUNK
}

// ---------------------------------------------------------------------------
// GEMM1: pair(6144x6144) = Xd^T Xw, K=256. Epilogue: LN stats per 32x32
// (i,l) block + raw pair stored as hi/lo bf16 in GEMM2 layout.
// ---------------------------------------------------------------------------
__global__ __launch_bounds__(256, 2) void gemm1_mma() {
    __shared__ char smem[SMEM_BYTES];
    const uint32_t sb = smem_u32(smem);

    float acc[4][4][4];
#pragma unroll
    for (int a = 0; a < 4; ++a)
#pragma unroll
        for (int b = 0; b < 4; ++b)
#pragma unroll
            for (int d = 0; d < 4; ++d) acc[a][b][d] = 0.f;

    const int r0 = blockIdx.y * 128, c0 = blockIdx.x * 128;
    mainloop(sb, NDIM / 16,
             g_Ah + (size_t)r0 * NDIM, g_Al + (size_t)r0 * NDIM, NDIM,
             g_Bh + (size_t)c0 * NDIM, g_Bl + (size_t)c0 * NDIM, NDIM, acc);

    const int tid = threadIdx.x, lane = tid & 31;
    const int wr = tid >> 7, wc = (tid >> 5) & 3;

    // Warp covers rows wr*64..+63 (2 LN i-blocks), cols wc*32..+31 (1 l-block).
#pragma unroll
    for (int b = 0; b < 2; ++b) {
        float s = 0.f, q = 0.f;
#pragma unroll
        for (int mt2 = 0; mt2 < 2; ++mt2)
#pragma unroll
            for (int nt = 0; nt < 4; ++nt)
#pragma unroll
                for (int d = 0; d < 4; ++d) {
                    float v = acc[b * 2 + mt2][nt][d];
                    s += v;
                    q += v * v;
                }
#pragma unroll
        for (int o = 16; o; o >>= 1) {
            s += __shfl_xor_sync(0xFFFFFFFFu, s, o);
            q += __shfl_xor_sync(0xFFFFFFFFu, q, o);
        }
        const int i = blockIdx.y * 4 + wr * 2 + b;
        const int l = blockIdx.x * 4 + wc;
        if (lane == 0) {
            float mean = s * (1.0f / 1024.0f);
            float var = q * (1.0f / 1024.0f) - mean * mean;
            g_mu[i * LDIM + l] = mean;
            g_rs[i * LDIM + l] = rsqrtf(var + 1e-5f);
        }
        const size_t ro = (size_t)(i * LDIM + l) * D2;
#pragma unroll
        for (int mt2 = 0; mt2 < 2; ++mt2)
#pragma unroll
            for (int nt = 0; nt < 4; ++nt)
#pragma unroll
                for (int h = 0; h < 2; ++h) {
                    float v0 = acc[b * 2 + mt2][nt][h * 2 + 0];
                    float v1 = acc[b * 2 + mt2][nt][h * 2 + 1];
                    int j = mt2 * 16 + (lane >> 2) + 8 * h;
                    int m = nt * 8 + (lane & 3) * 2;
                    __nv_bfloat162 hh = __floats2bfloat162_rn(v0, v1);
                    *(uint32_t*)(g_Ph + ro + j * 32 + m) = *(uint32_t*)&hh;
                    __nv_bfloat162 ll = __floats2bfloat162_rn(
                        v0 - __bfloat162float(hh.x), v1 - __bfloat162float(hh.y));
                    *(uint32_t*)(g_Pl + ro + j * 32 + m) = *(uint32_t*)&ll;
                }
    }
}

// ---------------------------------------------------------------------------
// GEMM2: out(36864x128) = pair @ Wp, K=1024. Epilogue: folded layernorm.
// ---------------------------------------------------------------------------
__global__ __launch_bounds__(256, 2) void gemm2_mma(float* __restrict__ out) {
    __shared__ char smem[SMEM_BYTES];
    const uint32_t sb = smem_u32(smem);

    float acc[4][4][4];
#pragma unroll
    for (int a = 0; a < 4; ++a)
#pragma unroll
        for (int b = 0; b < 4; ++b)
#pragma unroll
            for (int d = 0; d < 4; ++d) acc[a][b][d] = 0.f;

    const int row0 = blockIdx.x * 128;
    mainloop(sb, D2 / 16,
             g_Ph + (size_t)row0 * D2, g_Pl + (size_t)row0 * D2, D2,
             g_Wth, g_Wtl, D2, acc);

    const int tid = threadIdx.x, lane = tid & 31;
    const int wr = tid >> 7, wc = (tid >> 5) & 3;

    float c1v[4][2], c2v[4][2];
#pragma unroll
    for (int nt = 0; nt < 4; ++nt)
#pragma unroll
        for (int e = 0; e < 2; ++e) {
            int f = wc * 32 + nt * 8 + (lane & 3) * 2 + e;
            c1v[nt][e] = g_c1[f];
            c2v[nt][e] = g_c2[f];
        }
#pragma unroll
    for (int mt = 0; mt < 4; ++mt)
#pragma unroll
        for (int h = 0; h < 2; ++h) {
            int rr = row0 + wr * 64 + mt * 16 + (lane >> 2) + 8 * h;
            float rs = g_rs[rr];
            float tmu = rs * g_mu[rr];
#pragma unroll
            for (int nt = 0; nt < 4; ++nt) {
                float2 o;
                o.x = rs * acc[mt][nt][h * 2 + 0] - tmu * c1v[nt][0] + c2v[nt][0];
                o.y = rs * acc[mt][nt][h * 2 + 1] - tmu * c1v[nt][1] + c2v[nt][1];
                *(float2*)(out + (size_t)rr * FDIM + wc * 32 + nt * 8 + (lane & 3) * 2) = o;
            }
        }
}

// ---------------------------------------------------------------------------
// Prep: transpose+split x_down / x_down_w (256 x 6144 -> 6144 x 256 hi/lo)
// ---------------------------------------------------------------------------
__global__ __launch_bounds__(256) void split_xt(const float* __restrict__ xd,
                                                const float* __restrict__ xw) {
    __shared__ float t[32][33];
    const float* src = blockIdx.z ? xw : xd;
    __nv_bfloat16* dh = blockIdx.z ? g_Bh : g_Ah;
    __nv_bfloat16* dl = blockIdx.z ? g_Bl : g_Al;
    const int r0 = blockIdx.x * 32, n0 = blockIdx.y * 32;
    const int tx = threadIdx.x & 31, ty = threadIdx.x >> 5;
#pragma unroll
    for (int yy = 0; yy < 4; ++yy) {
        int n = n0 + ty + yy * 8;
        t[ty + yy * 8][tx] = src[(size_t)n * RDIM + r0 + tx];
    }
    __syncthreads();
#pragma unroll
    for (int yy = 0; yy < 4; ++yy) {
        int r = r0 + ty + yy * 8;
        float v = t[tx][ty + yy * 8];
        __nv_bfloat16 h = __float2bfloat16(v);
        dh[(size_t)r * NDIM + n0 + tx] = h;
        dl[(size_t)r * NDIM + n0 + tx] = __float2bfloat16(v - __bfloat162float(h));
    }
}

// Prep: Wp^T = (a2 (.) W)^T, split hi/lo, layout [f][k]
__global__ __launch_bounds__(256) void split_wt(const float* __restrict__ W,
                                                const float* __restrict__ a2) {
    __shared__ float t[32][33];
    const int k0 = blockIdx.x * 32, f0 = blockIdx.y * 32;
    const int tx = threadIdx.x & 31, ty = threadIdx.x >> 5;
#pragma unroll
    for (int yy = 0; yy < 4; ++yy) {
        int k = k0 + ty + yy * 8;
        t[ty + yy * 8][tx] = a2[k] * W[(size_t)k * FDIM + f0 + tx];
    }
    __syncthreads();
#pragma unroll
    for (int yy = 0; yy < 4; ++yy) {
        int f = f0 + ty + yy * 8;
        float v = t[tx][ty + yy * 8];
        __nv_bfloat16 h = __float2bfloat16(v);
        g_Wth[(size_t)f * D2 + k0 + tx] = h;
        g_Wtl[(size_t)f * D2 + k0 + tx] = __float2bfloat16(v - __bfloat162float(h));
    }
}

// Prep: c1[f] = sum_k a2[k] W[k][f];  c2[f] = sum_k b2[k] W[k][f] + b[f]
__global__ void prep_c_kernel(const float* __restrict__ a2, const float* __restrict__ b2,
                              const float* __restrict__ W, const float* __restrict__ b) {
    int f = threadIdx.x;  // 0..127
    float c1 = 0.f, c2 = 0.f;
#pragma unroll 8
    for (int k = 0; k < D2; ++k) {
        float w = W[k * FDIM + f];
        c1 += a2[k] * w;
        c2 += b2[k] * w;
    }
    g_c1[f] = c1;
    g_c2[f] = c2 + b[f];
}

// ---------------------------------------------------------------------------
extern "C" void kernel_launch(void* const* d_in, const int* in_sizes, int n_in,
                              void* d_out, int out_size) {
    const float* x_down   = (const float*)d_in[0];  // (1,256,192,32)
    const float* x_down_w = (const float*)d_in[1];
    const float* a2       = (const float*)d_in[2];  // (1024,)
    const float* b2       = (const float*)d_in[3];
    const float* W        = (const float*)d_in[4];  // (1024,128)
    const float* b        = (const float*)d_in[5];  // (128,)
    float* out = (float*)d_out;                     // (1,192,192,128)

    // Keep the L1/smem carveout high so two 48KB-smem CTAs co-reside per SM.
    cudaFuncSetAttribute(gemm1_mma, cudaFuncAttributePreferredSharedMemoryCarveout, 100);
    cudaFuncSetAttribute(gemm2_mma, cudaFuncAttributePreferredSharedMemoryCarveout, 100);

    split_xt<<<dim3(RDIM / 32, NDIM / 32, 2), 256>>>(x_down, x_down_w);
    split_wt<<<dim3(D2 / 32, FDIM / 32), 256>>>(W, a2);
    prep_c_kernel<<<1, 128>>>(a2, b2, W, b);
    gemm1_mma<<<dim3(48, 48), 256>>>();
    gemm2_mma<<<M2 / 128, 256>>>(out);
}

// round 10
// speedup vs baseline: 1.7715x; 1.7715x over previous
#include <cuda_runtime.h>
#include <cuda_bf16.h>
#include <stdint.h>

// Problem constants (B=1, N=256, L=192, J=32, d2=1024, F=128)
#define LDIM 192
#define NDIM 256      // K of GEMM1
#define RDIM 6144     // L*J  (M=N of GEMM1)
#define D2   1024     // J*J  (K of GEMM2)
#define FDIM 128      // N of GEMM2
#define M2   36864    // L*L  (M of GEMM2)

// ---------------------------------------------------------------------------
// Scratch (__device__ globals; no runtime allocation)
// ---------------------------------------------------------------------------
__device__ __nv_bfloat16 g_Ah[(size_t)RDIM * NDIM];   // x_down^T  hi  [r][n]
__device__ __nv_bfloat16 g_Al[(size_t)RDIM * NDIM];   //           lo
__device__ __nv_bfloat16 g_Bh[(size_t)RDIM * NDIM];   // x_down_w^T hi
__device__ __nv_bfloat16 g_Bl[(size_t)RDIM * NDIM];
__device__ __nv_bfloat16 g_Ph[(size_t)M2 * D2];       // pair hi [(i*192+l)][j*32+m]
__device__ __nv_bfloat16 g_Pl[(size_t)M2 * D2];       // pair lo
__device__ __nv_bfloat16 g_Wth[(size_t)FDIM * D2];    // (a2*W)^T hi [f][k]
__device__ __nv_bfloat16 g_Wtl[(size_t)FDIM * D2];
__device__ float g_mu[M2];
__device__ float g_rs[M2];
__device__ float g_c1[FDIM];
__device__ float g_c2[FDIM];

// ---------------------------------------------------------------------------
// Family-portable PTX helpers (compute_103-safe: mma.sync / ldmatrix / cp.async)
// ---------------------------------------------------------------------------
__device__ __forceinline__ uint32_t smem_u32(const void* p) {
    uint32_t a;
    asm("{ .reg .u64 t; cvta.to.shared.u64 t, %1; cvt.u32.u64 %0, t; }" : "=r"(a) : "l"(p));
    return a;
}
__device__ __forceinline__ void cp16(uint32_t dst, const void* src) {
    asm volatile("cp.async.cg.shared.global [%0], [%1], 16;" :: "r"(dst), "l"(src) : "memory");
}
__device__ __forceinline__ void cp_commit() {
    asm volatile("cp.async.commit_group;" ::: "memory");
}
template <int N>
__device__ __forceinline__ void cp_wait() {
    asm volatile("cp.async.wait_group %0;" :: "n"(N) : "memory");
}
__device__ __forceinline__ void ldm4(uint32_t a[4], uint32_t addr) {
    asm volatile("ldmatrix.sync.aligned.m8n8.x4.shared.b16 {%0,%1,%2,%3}, [%4];"
                 : "=r"(a[0]), "=r"(a[1]), "=r"(a[2]), "=r"(a[3]) : "r"(addr));
}
__device__ __forceinline__ void ldm2(uint32_t b[2], uint32_t addr) {
    asm volatile("ldmatrix.sync.aligned.m8n8.x2.shared.b16 {%0,%1}, [%2];"
                 : "=r"(b[0]), "=r"(b[1]) : "r"(addr));
}
__device__ __forceinline__ void mma16816(float c[4], const uint32_t a[4], const uint32_t b[2]) {
    asm volatile(
        "mma.sync.aligned.m16n8k16.row.col.f32.bf16.bf16.f32 "
        "{%0,%1,%2,%3}, {%4,%5,%6,%7}, {%8,%9}, {%0,%1,%2,%3};"
        : "+f"(c[0]), "+f"(c[1]), "+f"(c[2]), "+f"(c[3])
        : "r"(a[0]), "r"(a[1]), "r"(a[2]), "r"(a[3]), "r"(b[0]), "r"(b[1]));
}

// SMEM tile: 128 rows x 16 bf16 (32B/row), 2x16B chunks.
// Swizzle: chunk bit XOR (r>>2)&1. An 8-row ldmatrix phase at fixed chunk
// parity then touches 8 DISTINCT 16B slots mod 128B -> conflict-free.
// (r&1 variant left rows r and r+4 at the same bytes mod 128 = 2-way conflict.)
// cp.async stores: 8 lanes = rows 4r..4r+3 x 2 chunks = one full 128B line.
__device__ __forceinline__ uint32_t sw(int r, int c2) {
    return (uint32_t)(r * 32 + ((c2 ^ ((r >> 2) & 1)) << 4));
}

// SMEM layout per stage (16 KB): Ah[0:4K) Al[4K:8K) Bh[8K:12K) Bl[12K:16K)
#define STAGE_BYTES 16384
#define NSTAGE 3
#define SMEM_BYTES  (NSTAGE * STAGE_BYTES)   // 48 KB static

// ---------------------------------------------------------------------------
// Shared mainloop: 128x128 CTA tile, 8 warps (2x4), warp tile 64x32,
// K-chunk 16, 3-stage cp.async ring, one barrier per chunk,
// 3-MMA bf16 hi/lo split (split-major issue order).
// ---------------------------------------------------------------------------
__device__ __forceinline__ void mainloop(
    uint32_t sb, int NC,
    const __nv_bfloat16* __restrict__ Ah, const __nv_bfloat16* __restrict__ Al, int lda,
    const __nv_bfloat16* __restrict__ Bh, const __nv_bfloat16* __restrict__ Bl, int ldb,
    float acc[4][4][4])
{
    const int tid = threadIdx.x, lane = tid & 31;
    const int wr = tid >> 7;           // warp row 0..1 (64 rows each)
    const int wc = (tid >> 5) & 3;     // warp col 0..3 (32 cols each)

    // global->smem: 1 uint4 per tile per thread (256 threads = 128 rows x 2 chunks)
    const int r = tid >> 1, c2 = tid & 1;
    const uint32_t so = sw(r, c2);
    const char* pAh = (const char*)(Ah + (size_t)r * lda) + c2 * 16;
    const char* pAl = (const char*)(Al + (size_t)r * lda) + c2 * 16;
    const char* pBh = (const char*)(Bh + (size_t)r * ldb) + c2 * 16;
    const char* pBl = (const char*)(Bl + (size_t)r * ldb) + c2 * 16;

    // ldmatrix fragment base offsets.
    // Offsets +mt*512 / +nt*256 shift rows by 16/8 -> (r>>2)&1 parity unchanged.
    const uint32_t abase = sw(wr * 64 + (lane & 15), lane >> 4);
    const uint32_t bbase = sw(wc * 32 + (lane & 7), (lane >> 3) & 1);

#define ISSUE_CHUNK(ck, st) do {                                   \
        uint32_t _b = sb + (uint32_t)(st) * STAGE_BYTES;           \
        size_t _ko = (size_t)(ck) * 32;                            \
        cp16(_b + so,          pAh + _ko);                         \
        cp16(_b + 4096u + so,  pAl + _ko);                         \
        cp16(_b + 8192u + so,  pBh + _ko);                         \
        cp16(_b + 12288u + so, pBl + _ko);                         \
    } while (0)

    // prologue: chunks 0,1 -> stages 0,1
    ISSUE_CHUNK(0, 0); cp_commit();
    if (NC > 1) ISSUE_CHUNK(1, 1);
    cp_commit();

#pragma unroll 1
    for (int c = 0; c < NC; ++c) {
        const int st = c % NSTAGE;
        cp_wait<1>();          // chunk c resident
        __syncthreads();       // all warps done reading stage (c-1)%3

        const uint32_t Ab = sb + (uint32_t)st * STAGE_BYTES;
        const uint32_t Bb = Ab + 8192u;

        // B fragments first (frees the hazard window for the prefetch below)
        uint32_t bh[4][2], bl[4][2];
#pragma unroll
        for (int nt = 0; nt < 4; ++nt) {
            ldm2(bh[nt], Bb + bbase + nt * 256u);
            ldm2(bl[nt], Bb + 4096u + bbase + nt * 256u);
        }

        // prefetch chunk c+2 into stage (c+2)%3 == (c-1)%3 (safe: post-barrier)
        if (c + 2 < NC) ISSUE_CHUNK(c + 2, (c + 2) % NSTAGE);
        cp_commit();

#pragma unroll
        for (int mt = 0; mt < 4; ++mt) {
            uint32_t ah[4], al[4];
            ldm4(ah, Ab + abase + mt * 512u);
            ldm4(al, Ab + 4096u + abase + mt * 512u);
#pragma unroll
            for (int nt = 0; nt < 4; ++nt) mma16816(acc[mt][nt], ah, bh[nt]);  // hi*hi
#pragma unroll
            for (int nt = 0; nt < 4; ++nt) mma16816(acc[mt][nt], ah, bl[nt]);  // hi*lo
#pragma unroll
            for (int nt = 0; nt < 4; ++nt) mma16816(acc[mt][nt], al, bh[nt]);  // lo*hi
        }
    }
#undef ISSUE_CHUNK
}

// ---------------------------------------------------------------------------
// GEMM1: pair(6144x6144) = Xd^T Xw, K=256. Epilogue: LN stats per 32x32
// (i,l) block + raw pair stored as hi/lo bf16 in GEMM2 layout.
// ---------------------------------------------------------------------------
__global__ __launch_bounds__(256, 2) void gemm1_mma() {
    __shared__ char smem[SMEM_BYTES];
    const uint32_t sb = smem_u32(smem);

    float acc[4][4][4];
#pragma unroll
    for (int a = 0; a < 4; ++a)
#pragma unroll
        for (int b = 0; b < 4; ++b)
#pragma unroll
            for (int d = 0; d < 4; ++d) acc[a][b][d] = 0.f;

    const int r0 = blockIdx.y * 128, c0 = blockIdx.x * 128;
    mainloop(sb, NDIM / 16,
             g_Ah + (size_t)r0 * NDIM, g_Al + (size_t)r0 * NDIM, NDIM,
             g_Bh + (size_t)c0 * NDIM, g_Bl + (size_t)c0 * NDIM, NDIM, acc);

    const int tid = threadIdx.x, lane = tid & 31;
    const int wr = tid >> 7, wc = (tid >> 5) & 3;

    // Warp covers rows wr*64..+63 (2 LN i-blocks), cols wc*32..+31 (1 l-block).
#pragma unroll
    for (int b = 0; b < 2; ++b) {
        float s = 0.f, q = 0.f;
#pragma unroll
        for (int mt2 = 0; mt2 < 2; ++mt2)
#pragma unroll
            for (int nt = 0; nt < 4; ++nt)
#pragma unroll
                for (int d = 0; d < 4; ++d) {
                    float v = acc[b * 2 + mt2][nt][d];
                    s += v;
                    q += v * v;
                }
#pragma unroll
        for (int o = 16; o; o >>= 1) {
            s += __shfl_xor_sync(0xFFFFFFFFu, s, o);
            q += __shfl_xor_sync(0xFFFFFFFFu, q, o);
        }
        const int i = blockIdx.y * 4 + wr * 2 + b;
        const int l = blockIdx.x * 4 + wc;
        if (lane == 0) {
            float mean = s * (1.0f / 1024.0f);
            float var = q * (1.0f / 1024.0f) - mean * mean;
            g_mu[i * LDIM + l] = mean;
            g_rs[i * LDIM + l] = rsqrtf(var + 1e-5f);
        }
        const size_t ro = (size_t)(i * LDIM + l) * D2;
#pragma unroll
        for (int mt2 = 0; mt2 < 2; ++mt2)
#pragma unroll
            for (int nt = 0; nt < 4; ++nt)
#pragma unroll
                for (int h = 0; h < 2; ++h) {
                    float v0 = acc[b * 2 + mt2][nt][h * 2 + 0];
                    float v1 = acc[b * 2 + mt2][nt][h * 2 + 1];
                    int j = mt2 * 16 + (lane >> 2) + 8 * h;
                    int m = nt * 8 + (lane & 3) * 2;
                    __nv_bfloat162 hh = __floats2bfloat162_rn(v0, v1);
                    *(uint32_t*)(g_Ph + ro + j * 32 + m) = *(uint32_t*)&hh;
                    __nv_bfloat162 ll = __floats2bfloat162_rn(
                        v0 - __bfloat162float(hh.x), v1 - __bfloat162float(hh.y));
                    *(uint32_t*)(g_Pl + ro + j * 32 + m) = *(uint32_t*)&ll;
                }
    }
}

// ---------------------------------------------------------------------------
// GEMM2: out(36864x128) = pair @ Wp, K=1024. Epilogue: folded layernorm.
// ---------------------------------------------------------------------------
__global__ __launch_bounds__(256, 2) void gemm2_mma(float* __restrict__ out) {
    __shared__ char smem[SMEM_BYTES];
    const uint32_t sb = smem_u32(smem);

    float acc[4][4][4];
#pragma unroll
    for (int a = 0; a < 4; ++a)
#pragma unroll
        for (int b = 0; b < 4; ++b)
#pragma unroll
            for (int d = 0; d < 4; ++d) acc[a][b][d] = 0.f;

    const int row0 = blockIdx.x * 128;
    mainloop(sb, D2 / 16,
             g_Ph + (size_t)row0 * D2, g_Pl + (size_t)row0 * D2, D2,
             g_Wth, g_Wtl, D2, acc);

    const int tid = threadIdx.x, lane = tid & 31;
    const int wr = tid >> 7, wc = (tid >> 5) & 3;

    float c1v[4][2], c2v[4][2];
#pragma unroll
    for (int nt = 0; nt < 4; ++nt)
#pragma unroll
        for (int e = 0; e < 2; ++e) {
            int f = wc * 32 + nt * 8 + (lane & 3) * 2 + e;
            c1v[nt][e] = g_c1[f];
            c2v[nt][e] = g_c2[f];
        }
#pragma unroll
    for (int mt = 0; mt < 4; ++mt)
#pragma unroll
        for (int h = 0; h < 2; ++h) {
            int rr = row0 + wr * 64 + mt * 16 + (lane >> 2) + 8 * h;
            float rs = g_rs[rr];
            float tmu = rs * g_mu[rr];
#pragma unroll
            for (int nt = 0; nt < 4; ++nt) {
                float2 o;
                o.x = rs * acc[mt][nt][h * 2 + 0] - tmu * c1v[nt][0] + c2v[nt][0];
                o.y = rs * acc[mt][nt][h * 2 + 1] - tmu * c1v[nt][1] + c2v[nt][1];
                *(float2*)(out + (size_t)rr * FDIM + wc * 32 + nt * 8 + (lane & 3) * 2) = o;
            }
        }
}

// ---------------------------------------------------------------------------
// Prep: transpose+split x_down / x_down_w (256 x 6144 -> 6144 x 256 hi/lo)
// ---------------------------------------------------------------------------
__global__ __launch_bounds__(256) void split_xt(const float* __restrict__ xd,
                                                const float* __restrict__ xw) {
    __shared__ float t[32][33];
    const float* src = blockIdx.z ? xw : xd;
    __nv_bfloat16* dh = blockIdx.z ? g_Bh : g_Ah;
    __nv_bfloat16* dl = blockIdx.z ? g_Bl : g_Al;
    const int r0 = blockIdx.x * 32, n0 = blockIdx.y * 32;
    const int tx = threadIdx.x & 31, ty = threadIdx.x >> 5;
#pragma unroll
    for (int yy = 0; yy < 4; ++yy) {
        int n = n0 + ty + yy * 8;
        t[ty + yy * 8][tx] = src[(size_t)n * RDIM + r0 + tx];
    }
    __syncthreads();
#pragma unroll
    for (int yy = 0; yy < 4; ++yy) {
        int r = r0 + ty + yy * 8;
        float v = t[tx][ty + yy * 8];
        __nv_bfloat16 h = __float2bfloat16(v);
        dh[(size_t)r * NDIM + n0 + tx] = h;
        dl[(size_t)r * NDIM + n0 + tx] = __float2bfloat16(v - __bfloat162float(h));
    }
}

// Prep: Wp^T = (a2 (.) W)^T, split hi/lo, layout [f][k]
__global__ __launch_bounds__(256) void split_wt(const float* __restrict__ W,
                                                const float* __restrict__ a2) {
    __shared__ float t[32][33];
    const int k0 = blockIdx.x * 32, f0 = blockIdx.y * 32;
    const int tx = threadIdx.x & 31, ty = threadIdx.x >> 5;
#pragma unroll
    for (int yy = 0; yy < 4; ++yy) {
        int k = k0 + ty + yy * 8;
        t[ty + yy * 8][tx] = a2[k] * W[(size_t)k * FDIM + f0 + tx];
    }
    __syncthreads();
#pragma unroll
    for (int yy = 0; yy < 4; ++yy) {
        int f = f0 + ty + yy * 8;
        float v = t[tx][ty + yy * 8];
        __nv_bfloat16 h = __float2bfloat16(v);
        g_Wth[(size_t)f * D2 + k0 + tx] = h;
        g_Wtl[(size_t)f * D2 + k0 + tx] = __float2bfloat16(v - __bfloat162float(h));
    }
}

// Prep: c1[f] = sum_k a2[k] W[k][f];  c2[f] = sum_k b2[k] W[k][f] + b[f]
__global__ void prep_c_kernel(const float* __restrict__ a2, const float* __restrict__ b2,
                              const float* __restrict__ W, const float* __restrict__ b) {
    int f = threadIdx.x;  // 0..127
    float c1 = 0.f, c2 = 0.f;
#pragma unroll 8
    for (int k = 0; k < D2; ++k) {
        float w = W[k * FDIM + f];
        c1 += a2[k] * w;
        c2 += b2[k] * w;
    }
    g_c1[f] = c1;
    g_c2[f] = c2 + b[f];
}

// ---------------------------------------------------------------------------
extern "C" void kernel_launch(void* const* d_in, const int* in_sizes, int n_in,
                              void* d_out, int out_size) {
    const float* x_down   = (const float*)d_in[0];  // (1,256,192,32)
    const float* x_down_w = (const float*)d_in[1];
    const float* a2       = (const float*)d_in[2];  // (1024,)
    const float* b2       = (const float*)d_in[3];
    const float* W        = (const float*)d_in[4];  // (1024,128)
    const float* b        = (const float*)d_in[5];  // (128,)
    float* out = (float*)d_out;                     // (1,192,192,128)

    // Keep the L1/smem carveout high so two 48KB-smem CTAs co-reside per SM.
    cudaFuncSetAttribute(gemm1_mma, cudaFuncAttributePreferredSharedMemoryCarveout, 100);
    cudaFuncSetAttribute(gemm2_mma, cudaFuncAttributePreferredSharedMemoryCarveout, 100);

    split_xt<<<dim3(RDIM / 32, NDIM / 32, 2), 256>>>(x_down, x_down_w);
    split_wt<<<dim3(D2 / 32, FDIM / 32), 256>>>(W, a2);
    prep_c_kernel<<<1, 128>>>(a2, b2, W, b);
    gemm1_mma<<<dim3(48, 48), 256>>>();
    gemm2_mma<<<M2 / 128, 256>>>(out);
}